// round 1
// baseline (speedup 1.0000x reference)
#include <cuda_runtime.h>
#include <math.h>

#define B 8
#define D 4096
#define H 32
#define KVH 8
#define HD 128
#define M 4096
#define NREP 4
#define NCOLS (H*HD + 2*KVH*HD)   /* 6144 */
#define NSPLIT1 4
#define ICHUNK (D/NSPLIT1)        /* 1024 */
#define MSPLIT 8
#define MC (M/MSPLIT)             /* 512 */
#define SCALE 0.08838834764831845f
#define FULLMASK 0xffffffffu

// ---------------- static device scratch (no allocations allowed) ----------------
__device__ float g_qkv_part[NSPLIT1][B][NCOLS];
__device__ float g_q[B][H*HD];
__device__ float g_knew[B][KVH][HD];
__device__ float g_vnew[B][KVH][HD];
__device__ float g_part_o[B][KVH][MSPLIT][NREP][HD];
__device__ float g_part_m[B][KVH][MSPLIT][NREP];
__device__ float g_part_l[B][KVH][MSPLIT][NREP];
__device__ float g_attn[B][D];
__device__ float g_out_part[NSPLIT1][B][D];

// ---------------- kernel 1: QKV projection (split-K GEMV, all 8 batches) ----------------
__global__ void proj_qkv(const float* __restrict__ x, const float* __restrict__ wq,
                         const float* __restrict__ wk, const float* __restrict__ wv) {
    __shared__ float xs[B][ICHUNK];
    const int tid = threadIdx.x;
    const int j = blockIdx.x * 128 + tid;
    const int i0 = blockIdx.y * ICHUNK;

    for (int idx = tid; idx < B * ICHUNK; idx += 128) {
        int b = idx / ICHUNK, ii = idx % ICHUNK;
        xs[b][ii] = x[b * D + i0 + ii];
    }
    __syncthreads();

    // column -> which weight matrix (block-uniform: boundaries are multiples of 128)
    const float* w; int stride, jl;
    if (j < H*HD)                 { w = wq; stride = H*HD;  jl = j; }
    else if (j < H*HD + KVH*HD)   { w = wk; stride = KVH*HD; jl = j - H*HD; }
    else                          { w = wv; stride = KVH*HD; jl = j - H*HD - KVH*HD; }
    const float* wp = w + (size_t)i0 * stride + jl;

    float acc[B];
    #pragma unroll
    for (int b = 0; b < B; b++) acc[b] = 0.f;

    #pragma unroll 8
    for (int ii = 0; ii < ICHUNK; ii++) {
        float wvv = wp[(size_t)ii * stride];
        #pragma unroll
        for (int b = 0; b < B; b++) acc[b] = fmaf(xs[b][ii], wvv, acc[b]);
    }
    #pragma unroll
    for (int b = 0; b < B; b++) g_qkv_part[blockIdx.y][b][j] = acc[b];
}

// ---------------- kernel 2: reduce partials + RoPE + scatter ----------------
__global__ void rope_scatter(const float* __restrict__ fcos, const float* __restrict__ fsin) {
    const int t = blockIdx.x * 128 + threadIdx.x;        // pair id over B*NCOLS/2
    const int b  = t / (NCOLS / 2);
    const int pj = t % (NCOLS / 2);
    const int j0 = 2 * pj;

    float v0 = 0.f, v1 = 0.f;
    #pragma unroll
    for (int s = 0; s < NSPLIT1; s++) {
        v0 += g_qkv_part[s][b][j0];
        v1 += g_qkv_part[s][b][j0 + 1];
    }

    if (j0 < H*HD) {                                      // q + RoPE
        int p = (j0 & (HD-1)) >> 1;
        float c = fcos[p], s_ = fsin[p];
        g_q[b][j0]     = v0 * c - v1 * s_;
        g_q[b][j0 + 1] = v0 * s_ + v1 * c;
    } else if (j0 < H*HD + KVH*HD) {                      // k + RoPE
        int l = j0 - H*HD; int kvh = l >> 7; int d = l & (HD-1); int p = d >> 1;
        float c = fcos[p], s_ = fsin[p];
        g_knew[b][kvh][d]     = v0 * c - v1 * s_;
        g_knew[b][kvh][d + 1] = v0 * s_ + v1 * c;
    } else {                                              // v (no RoPE)
        int l = j0 - H*HD - KVH*HD; int kvh = l >> 7; int d = l & (HD-1);
        g_vnew[b][kvh][d]     = v0;
        g_vnew[b][kvh][d + 1] = v1;
    }
}

// ---------------- kernel 3: flash-decode attention, fused with cache emit ----------------
__global__ void attn_pass1(const float* __restrict__ cache_k, const float* __restrict__ cache_v,
                           const float* __restrict__ mask, const int* __restrict__ pos_p,
                           float* __restrict__ out_k, float* __restrict__ out_v) {
    const int bx = blockIdx.x;
    const int split = bx % MSPLIT;
    const int kvh = (bx / MSPLIT) % KVH;
    const int b = bx / (MSPLIT * KVH);
    const int tid = threadIdx.x, lane = tid & 31, wid = tid >> 5;
    const int pos = pos_p[0];

    const size_t base = (size_t)(b * KVH + kvh) * M * HD;
    const float* Kc = cache_k + base;
    const float* Vc = cache_v + base;
    float* Ko = out_k + base;
    float* Vo = out_v + base;
    const float* mb = mask + ((size_t)(b * H) + kvh * NREP) * M;

    float4 q4[NREP];
    #pragma unroll
    for (int h = 0; h < NREP; h++)
        q4[h] = *(const float4*)&g_q[b][(kvh * NREP + h) * HD + 4 * lane];

    float rmax[NREP], rsum[NREP];
    float4 oacc[NREP];
    #pragma unroll
    for (int h = 0; h < NREP; h++) {
        rmax[h] = -1e30f; rsum[h] = 0.f;
        oacc[h] = make_float4(0.f, 0.f, 0.f, 0.f);
    }

    const int m0 = split * MC;
    for (int m = m0 + wid; m < m0 + MC; m += 4) {
        const float* krow = (m == pos) ? &g_knew[b][kvh][0] : (Kc + (size_t)m * HD);
        const float* vrow = (m == pos) ? &g_vnew[b][kvh][0] : (Vc + (size_t)m * HD);
        float4 k4 = *(const float4*)(krow + 4 * lane);
        float4 v4 = *(const float4*)(vrow + 4 * lane);
        // emit updated cache to output while it's in registers
        *(float4*)(Ko + (size_t)m * HD + 4 * lane) = k4;
        *(float4*)(Vo + (size_t)m * HD + 4 * lane) = v4;

        float mval = (lane < NREP) ? mb[(size_t)lane * M + m] : 0.f;

        float s[NREP];
        #pragma unroll
        for (int h = 0; h < NREP; h++) {
            float t = q4[h].x * k4.x + q4[h].y * k4.y + q4[h].z * k4.z + q4[h].w * k4.w;
            #pragma unroll
            for (int off = 16; off; off >>= 1) t += __shfl_xor_sync(FULLMASK, t, off);
            s[h] = t * SCALE + __shfl_sync(FULLMASK, mval, h);
        }
        #pragma unroll
        for (int h = 0; h < NREP; h++) {
            float nm = fmaxf(rmax[h], s[h]);
            float corr = __expf(rmax[h] - nm);
            float p = __expf(s[h] - nm);
            rmax[h] = nm;
            rsum[h] = rsum[h] * corr + p;
            oacc[h].x = oacc[h].x * corr + p * v4.x;
            oacc[h].y = oacc[h].y * corr + p * v4.y;
            oacc[h].z = oacc[h].z * corr + p * v4.z;
            oacc[h].w = oacc[h].w * corr + p * v4.w;
        }
    }

    // CTA combine: 4 warps -> 1 partial per (b, kvh, split)
    __shared__ float smax[4][NREP], ssum[4][NREP];
    __shared__ float so[4][NREP][HD];
    #pragma unroll
    for (int h = 0; h < NREP; h++)
        *(float4*)&so[wid][h][4 * lane] = oacc[h];
    if (lane == 0) {
        #pragma unroll
        for (int h = 0; h < NREP; h++) { smax[wid][h] = rmax[h]; ssum[wid][h] = rsum[h]; }
    }
    __syncthreads();

    const int d = tid;  // 0..127
    #pragma unroll
    for (int h = 0; h < NREP; h++) {
        float Mx = fmaxf(fmaxf(smax[0][h], smax[1][h]), fmaxf(smax[2][h], smax[3][h]));
        float L = 0.f, O = 0.f;
        #pragma unroll
        for (int w = 0; w < 4; w++) {
            float e = __expf(smax[w][h] - Mx);
            L += ssum[w][h] * e;
            O += so[w][h][d] * e;
        }
        g_part_o[b][kvh][split][h][d] = O;
        if (d == 0) { g_part_m[b][kvh][split][h] = Mx; g_part_l[b][kvh][split][h] = L; }
    }
}

// ---------------- kernel 4: combine m-splits ----------------
__global__ void attn_reduce() {
    const int bx = blockIdx.x;
    const int kvh = bx % KVH;
    const int b = bx / KVH;
    const int d = threadIdx.x;
    #pragma unroll
    for (int h = 0; h < NREP; h++) {
        float Mx = -1e30f;
        #pragma unroll
        for (int s = 0; s < MSPLIT; s++) Mx = fmaxf(Mx, g_part_m[b][kvh][s][h]);
        float L = 0.f, O = 0.f;
        #pragma unroll
        for (int s = 0; s < MSPLIT; s++) {
            float e = __expf(g_part_m[b][kvh][s][h] - Mx);
            L += g_part_l[b][kvh][s][h] * e;
            O += g_part_o[b][kvh][s][h][d] * e;
        }
        g_attn[b][(kvh * NREP + h) * HD + d] = O / L;
    }
}

// ---------------- kernel 5: output projection (split-K GEMV) ----------------
__global__ void oproj(const float* __restrict__ wo) {
    __shared__ float xs[B][ICHUNK];
    const int tid = threadIdx.x;
    const int j = blockIdx.x * 128 + tid;
    const int i0 = blockIdx.y * ICHUNK;

    for (int idx = tid; idx < B * ICHUNK; idx += 128) {
        int b = idx / ICHUNK, ii = idx % ICHUNK;
        xs[b][ii] = g_attn[b][i0 + ii];
    }
    __syncthreads();

    const float* wp = wo + (size_t)i0 * D + j;
    float acc[B];
    #pragma unroll
    for (int b = 0; b < B; b++) acc[b] = 0.f;
    #pragma unroll 8
    for (int ii = 0; ii < ICHUNK; ii++) {
        float wvv = wp[(size_t)ii * D];
        #pragma unroll
        for (int b = 0; b < B; b++) acc[b] = fmaf(xs[b][ii], wvv, acc[b]);
    }
    #pragma unroll
    for (int b = 0; b < B; b++) g_out_part[blockIdx.y][b][j] = acc[b];
}

// ---------------- kernel 6: final reduce -> d_out ----------------
__global__ void oproj_reduce(float* __restrict__ out) {
    const int t = blockIdx.x * 128 + threadIdx.x;
    const int b = t / D, j = t % D;
    float a = 0.f;
    #pragma unroll
    for (int s = 0; s < NSPLIT1; s++) a += g_out_part[s][b][j];
    out[(size_t)b * D + j] = a;
}

// ---------------- launch ----------------
extern "C" void kernel_launch(void* const* d_in, const int* in_sizes, int n_in,
                              void* d_out, int out_size) {
    // metadata order: x, freqs_cos, freqs_sin, mask, cache_k, cache_v,
    //                 prefill, input_indexes, cache_indexes, wq, wk, wv, wo
    const float* x        = (const float*)d_in[0];
    const float* fcos     = (const float*)d_in[1];
    const float* fsin     = (const float*)d_in[2];
    const float* mask     = (const float*)d_in[3];
    const float* cache_k  = (const float*)d_in[4];
    const float* cache_v  = (const float*)d_in[5];
    const int*   in_idx   = (const int*)d_in[7];
    const float* wq       = (const float*)d_in[9];
    const float* wk       = (const float*)d_in[10];
    const float* wv       = (const float*)d_in[11];
    const float* wo       = (const float*)d_in[12];

    float* out   = (float*)d_out;                       // [B*D]
    float* out_k = out + (size_t)B * D;                 // [B*KVH*M*HD]
    float* out_v = out_k + (size_t)B * KVH * M * HD;    // [B*KVH*M*HD]

    proj_qkv<<<dim3(NCOLS / 128, NSPLIT1), 128>>>(x, wq, wk, wv);
    rope_scatter<<<(B * NCOLS / 2) / 128, 128>>>(fcos, fsin);
    attn_pass1<<<B * KVH * MSPLIT, 128>>>(cache_k, cache_v, mask, in_idx, out_k, out_v);
    attn_reduce<<<B * KVH, 128>>>();
    oproj<<<dim3(D / 128, NSPLIT1), 128>>>(wo);
    oproj_reduce<<<(B * D) / 128, 128>>>(out);
}

// round 2
// speedup vs baseline: 1.9670x; 1.9670x over previous
#include <cuda_runtime.h>
#include <math.h>

#define B 8
#define D 4096
#define H 32
#define KVH 8
#define HD 128
#define M 4096
#define NREP 4
#define NCOLS (H*HD + 2*KVH*HD)   /* 6144 */
#define NSPLIT1 16
#define ICHUNK (D/NSPLIT1)        /* 256 */
#define MSPLIT 16
#define MC (M/MSPLIT)             /* 256 */
#define TILE 64
#define NT (MC/TILE)              /* 4 */
#define SCALE 0.08838834764831845f
#define FULLMASK 0xffffffffu

// smem layout (floats) for attn kernel
#define SM_KS   0                  /* 64*33 float4 = 8448 floats */
#define SM_VS   8448
#define SM_Q    16896              /* 512 */
#define SM_SC   17408              /* [64][4] = 256 */
#define SM_PS   17664              /* 256 */
#define SM_RMX  17920              /* 4 */
#define SM_RSM  17924              /* 4 */
#define SM_CR   17928              /* 4 */
#define SM_FLOATS 17936
#define SMEM_BYTES (SM_FLOATS*4)

// ---------------- static device scratch ----------------
__device__ __align__(16) float g_qkv_part[NSPLIT1][B][NCOLS];
__device__ __align__(16) float g_q[B][H*HD];
__device__ __align__(16) float g_knew[B][KVH][HD];
__device__ __align__(16) float g_vnew[B][KVH][HD];
__device__ __align__(16) float g_part_o[B][KVH][MSPLIT][NREP][HD];
__device__ float g_part_m[B][KVH][MSPLIT][NREP];
__device__ float g_part_l[B][KVH][MSPLIT][NREP];
__device__ __align__(16) float g_attn[B][D];
__device__ __align__(16) float g_out_part[NSPLIT1][B][D];

// ---------------- kernel 1: QKV projection (split-K GEMV) ----------------
__global__ __launch_bounds__(256) void proj_qkv(const float* __restrict__ x,
                         const float* __restrict__ wq,
                         const float* __restrict__ wk, const float* __restrict__ wv) {
    __shared__ float xs[B][ICHUNK];
    const int tid = threadIdx.x;
    const int j = blockIdx.x * 256 + tid;
    const int i0 = blockIdx.y * ICHUNK;

    for (int idx = tid; idx < B * ICHUNK; idx += 256) {
        int b = idx / ICHUNK, ii = idx % ICHUNK;
        xs[b][ii] = x[b * D + i0 + ii];
    }
    __syncthreads();

    const float* w; int stride, jl;
    if (j < H*HD)                 { w = wq; stride = H*HD;  jl = j; }
    else if (j < H*HD + KVH*HD)   { w = wk; stride = KVH*HD; jl = j - H*HD; }
    else                          { w = wv; stride = KVH*HD; jl = j - H*HD - KVH*HD; }
    const float* wp = w + (size_t)i0 * stride + jl;

    float acc[B];
    #pragma unroll
    for (int b = 0; b < B; b++) acc[b] = 0.f;

    #pragma unroll 8
    for (int ii = 0; ii < ICHUNK; ii++) {
        float wvv = wp[(size_t)ii * stride];
        #pragma unroll
        for (int b = 0; b < B; b++) acc[b] = fmaf(xs[b][ii], wvv, acc[b]);
    }
    #pragma unroll
    for (int b = 0; b < B; b++) g_qkv_part[blockIdx.y][b][j] = acc[b];
}

// ---------------- kernel 2: reduce partials + RoPE + scatter ----------------
__global__ void rope_scatter(const float* __restrict__ fcos, const float* __restrict__ fsin) {
    const int t = blockIdx.x * 128 + threadIdx.x;
    const int b  = t / (NCOLS / 2);
    const int pj = t % (NCOLS / 2);
    const int j0 = 2 * pj;

    float v0 = 0.f, v1 = 0.f;
    #pragma unroll
    for (int s = 0; s < NSPLIT1; s++) {
        v0 += g_qkv_part[s][b][j0];
        v1 += g_qkv_part[s][b][j0 + 1];
    }

    if (j0 < H*HD) {                                      // q + RoPE, pre-scaled
        int p = (j0 & (HD-1)) >> 1;
        float c = fcos[p] * SCALE, s_ = fsin[p] * SCALE;
        g_q[b][j0]     = v0 * c - v1 * s_;
        g_q[b][j0 + 1] = v0 * s_ + v1 * c;
    } else if (j0 < H*HD + KVH*HD) {                      // k + RoPE
        int l = j0 - H*HD; int kvh = l >> 7; int d = l & (HD-1); int p = d >> 1;
        float c = fcos[p], s_ = fsin[p];
        g_knew[b][kvh][d]     = v0 * c - v1 * s_;
        g_knew[b][kvh][d + 1] = v0 * s_ + v1 * c;
    } else {                                              // v
        int l = j0 - H*HD - KVH*HD; int kvh = l >> 7; int d = l & (HD-1);
        g_vnew[b][kvh][d]     = v0;
        g_vnew[b][kvh][d + 1] = v1;
    }
}

// ---------------- kernel 3: tiled flash-decode attention + cache emit ----------------
__global__ __launch_bounds__(256, 3) void attn_pass1(
        const float* __restrict__ cache_k, const float* __restrict__ cache_v,
        const float* __restrict__ mask, const int* __restrict__ pos_p,
        float* __restrict__ out_k, float* __restrict__ out_v) {
    extern __shared__ float sm[];
    float4* Ks4 = (float4*)sm;
    float4* Vs4 = (float4*)(sm + SM_VS);
    float*  Qs  = sm + SM_Q;
    float*  sc  = sm + SM_SC;
    float*  ps  = sm + SM_PS;
    float*  rmx = sm + SM_RMX;
    float*  rsm = sm + SM_RSM;
    float*  cr  = sm + SM_CR;

    const int bx = blockIdx.x;
    const int split = bx % MSPLIT;
    const int kvh = (bx / MSPLIT) % KVH;
    const int b = bx / (MSPLIT * KVH);
    const int tid = threadIdx.x;
    const int pos = pos_p[0];

    const size_t base = (size_t)(b * KVH + kvh) * M * HD;
    const float4* Kg = (const float4*)(cache_k + base);
    const float4* Vg = (const float4*)(cache_v + base);
    float4* Kog = (float4*)(out_k + base);
    float4* Vog = (float4*)(out_v + base);
    const float4* knew4 = (const float4*)&g_knew[b][kvh][0];
    const float4* vnew4 = (const float4*)&g_vnew[b][kvh][0];

    // per-thread fixed roles
    const int r  = tid & 63;          // score row
    const int h  = tid >> 6;          // score head
    const int d  = tid & 127;         // accum dim
    const int hp = tid >> 7;          // accum head-pair
    const int h0 = hp * 2, h1 = h0 + 1;
    const float* maskp = mask + ((size_t)(b * H) + kvh * NREP + h) * M;

    // init
    if (tid < 4) { rmx[tid] = -1e30f; rsm[tid] = 0.f; }
    for (int idx = tid; idx < NREP * HD; idx += 256)
        Qs[idx] = g_q[b][kvh * NREP * HD + idx];

    float o0 = 0.f, o1 = 0.f;

    for (int t = 0; t < NT; t++) {
        const int m0 = split * MC + t * TILE;
        const int fb = m0 * 32;   // float4 base index of tile

        // ---- copy K tile: gmem -> smem + out ----
        {
            float4 buf[8];
            #pragma unroll
            for (int i = 0; i < 8; i++) buf[i] = Kg[fb + tid + i * 256];
            #pragma unroll
            for (int i = 0; i < 8; i++) {
                int f = tid + i * 256;
                int row = f >> 5, c4 = f & 31;
                if (m0 + row == pos) buf[i] = knew4[c4];
                Ks4[row * 33 + c4] = buf[i];
                Kog[fb + f] = buf[i];
            }
        }
        // ---- copy V tile ----
        {
            float4 buf[8];
            #pragma unroll
            for (int i = 0; i < 8; i++) buf[i] = Vg[fb + tid + i * 256];
            #pragma unroll
            for (int i = 0; i < 8; i++) {
                int f = tid + i * 256;
                int row = f >> 5, c4 = f & 31;
                if (m0 + row == pos) buf[i] = vnew4[c4];
                Vs4[row * 33 + c4] = buf[i];
                Vog[fb + f] = buf[i];
            }
        }
        __syncthreads();

        // ---- scores: one (row, head) per thread ----
        {
            const float4* krow = Ks4 + r * 33;
            const float4* qrow = (const float4*)Qs + h * 32;
            float acc = 0.f;
            #pragma unroll
            for (int i = 0; i < 32; i++) {
                float4 k = krow[i];
                float4 q = qrow[i];
                acc = fmaf(k.x, q.x, acc);
                acc = fmaf(k.y, q.y, acc);
                acc = fmaf(k.z, q.z, acc);
                acc = fmaf(k.w, q.w, acc);
            }
            sc[r * 4 + h] = acc + maskp[m0 + r];
        }
        __syncthreads();

        // ---- tile max + running max/correction ----
        if (tid < 128) {
            int hh = tid >> 5, ln = tid & 31;
            float v = fmaxf(sc[ln * 4 + hh], sc[(ln + 32) * 4 + hh]);
            #pragma unroll
            for (int off = 16; off; off >>= 1)
                v = fmaxf(v, __shfl_xor_sync(FULLMASK, v, off));
            if (ln == 0) {
                float nm = fmaxf(rmx[hh], v);
                cr[hh] = __expf(rmx[hh] - nm);
                rmx[hh] = nm;
            }
        }
        __syncthreads();

        // ---- p = exp(s - max) ----
        ps[r * 4 + h] = __expf(sc[r * 4 + h] - rmx[h]);
        __syncthreads();

        // ---- running sum (warps 0-3) ----
        if (tid < 128) {
            int hh = tid >> 5, ln = tid & 31;
            float v = ps[ln * 4 + hh] + ps[(ln + 32) * 4 + hh];
            #pragma unroll
            for (int off = 16; off; off >>= 1)
                v += __shfl_xor_sync(FULLMASK, v, off);
            if (ln == 0) rsm[hh] = rsm[hh] * cr[hh] + v;
        }
        // ---- accumulate: 2 heads per thread at dim d ----
        {
            const float* Vf = (const float*)Vs4;
            o0 *= cr[h0];
            o1 *= cr[h1];
            #pragma unroll 4
            for (int m = 0; m < TILE; m++) {
                float vv = Vf[m * 132 + d];
                o0 = fmaf(ps[m * 4 + h0], vv, o0);
                o1 = fmaf(ps[m * 4 + h1], vv, o1);
            }
        }
        __syncthreads();
    }

    g_part_o[b][kvh][split][h0][d] = o0;
    g_part_o[b][kvh][split][h1][d] = o1;
    if (tid < 4) {
        g_part_m[b][kvh][split][tid] = rmx[tid];
        g_part_l[b][kvh][split][tid] = rsm[tid];
    }
}

// ---------------- kernel 4: combine m-splits ----------------
__global__ void attn_reduce() {
    const int bx = blockIdx.x;
    const int kvh = bx % KVH;
    const int b = bx / KVH;
    const int d = threadIdx.x;
    #pragma unroll
    for (int h = 0; h < NREP; h++) {
        float Mx = -1e30f;
        #pragma unroll
        for (int s = 0; s < MSPLIT; s++) Mx = fmaxf(Mx, g_part_m[b][kvh][s][h]);
        float L = 0.f, O = 0.f;
        #pragma unroll
        for (int s = 0; s < MSPLIT; s++) {
            float e = __expf(g_part_m[b][kvh][s][h] - Mx);
            L += g_part_l[b][kvh][s][h] * e;
            O += g_part_o[b][kvh][s][h][d] * e;
        }
        g_attn[b][(kvh * NREP + h) * HD + d] = O / L;
    }
}

// ---------------- kernel 5: output projection (split-K GEMV) ----------------
__global__ __launch_bounds__(256) void oproj(const float* __restrict__ wo) {
    __shared__ float xs[B][ICHUNK];
    const int tid = threadIdx.x;
    const int j = blockIdx.x * 256 + tid;
    const int i0 = blockIdx.y * ICHUNK;

    for (int idx = tid; idx < B * ICHUNK; idx += 256) {
        int b = idx / ICHUNK, ii = idx % ICHUNK;
        xs[b][ii] = g_attn[b][i0 + ii];
    }
    __syncthreads();

    const float* wp = wo + (size_t)i0 * D + j;
    float acc[B];
    #pragma unroll
    for (int b = 0; b < B; b++) acc[b] = 0.f;
    #pragma unroll 8
    for (int ii = 0; ii < ICHUNK; ii++) {
        float wvv = wp[(size_t)ii * D];
        #pragma unroll
        for (int b = 0; b < B; b++) acc[b] = fmaf(xs[b][ii], wvv, acc[b]);
    }
    #pragma unroll
    for (int b = 0; b < B; b++) g_out_part[blockIdx.y][b][j] = acc[b];
}

// ---------------- kernel 6: final reduce -> d_out ----------------
__global__ void oproj_reduce(float* __restrict__ out) {
    const int t = blockIdx.x * 128 + threadIdx.x;
    const int b = t / D, j = t % D;
    float a = 0.f;
    #pragma unroll
    for (int s = 0; s < NSPLIT1; s++) a += g_out_part[s][b][j];
    out[(size_t)b * D + j] = a;
}

// ---------------- launch ----------------
extern "C" void kernel_launch(void* const* d_in, const int* in_sizes, int n_in,
                              void* d_out, int out_size) {
    const float* x        = (const float*)d_in[0];
    const float* fcos     = (const float*)d_in[1];
    const float* fsin     = (const float*)d_in[2];
    const float* mask     = (const float*)d_in[3];
    const float* cache_k  = (const float*)d_in[4];
    const float* cache_v  = (const float*)d_in[5];
    const int*   in_idx   = (const int*)d_in[7];
    const float* wq       = (const float*)d_in[9];
    const float* wk       = (const float*)d_in[10];
    const float* wv       = (const float*)d_in[11];
    const float* wo       = (const float*)d_in[12];

    float* out   = (float*)d_out;
    float* out_k = out + (size_t)B * D;
    float* out_v = out_k + (size_t)B * KVH * M * HD;

    cudaFuncSetAttribute(attn_pass1, cudaFuncAttributeMaxDynamicSharedMemorySize, SMEM_BYTES);

    proj_qkv<<<dim3(NCOLS / 256, NSPLIT1), 256>>>(x, wq, wk, wv);
    rope_scatter<<<(B * NCOLS / 2) / 128, 128>>>(fcos, fsin);
    attn_pass1<<<B * KVH * MSPLIT, 256, SMEM_BYTES>>>(cache_k, cache_v, mask, in_idx, out_k, out_v);
    attn_reduce<<<B * KVH, 128>>>();
    oproj<<<dim3(D / 256, NSPLIT1), 256>>>(wo);
    oproj_reduce<<<(B * D) / 128, 128>>>(out);
}

// round 3
// speedup vs baseline: 2.2455x; 1.1416x over previous
#include <cuda_runtime.h>
#include <math.h>

#define B 8
#define D 4096
#define H 32
#define KVH 8
#define HD 128
#define M 4096
#define NREP 4
#define NCOLS (H*HD + 2*KVH*HD)   /* 6144 */
#define NSPLIT1 32
#define ICHUNK (D/NSPLIT1)        /* 128 */
#define MSPLIT 32
#define MC (M/MSPLIT)             /* 128 */
#define TILE 32
#define NT (MC/TILE)              /* 4 */
#define SCALE 0.08838834764831845f
#define FULLMASK 0xffffffffu

// attn smem layout (floats): two buffers of [K(32x33 f4) | V(32x33 f4)]
#define BUF_F (2*32*33*4)          /* 8448 floats per buffer */
#define SM_Q    (2*BUF_F)          /* 16896 */
#define SM_SC   (SM_Q+512)         /* 17408: [32][4] */
#define SM_PS   (SM_SC+128)        /* 17536 */
#define SM_RMX  (SM_PS+128)
#define SM_RSM  (SM_RMX+4)
#define SM_CR   (SM_RSM+4)
#define SM_FLOATS (SM_CR+4)
#define SMEM_BYTES (SM_FLOATS*4)   /* 70704 B */

// ---------------- static device scratch ----------------
__device__ __align__(16) float g_qkv_part[NSPLIT1][B][NCOLS];
__device__ __align__(16) float g_q[B][H*HD];
__device__ __align__(16) float g_knew[B][KVH][HD];
__device__ __align__(16) float g_vnew[B][KVH][HD];
__device__ __align__(16) float g_part_o[B][KVH][MSPLIT][NREP][HD];
__device__ float g_part_m[B][KVH][MSPLIT][NREP];
__device__ float g_part_l[B][KVH][MSPLIT][NREP];
__device__ __align__(16) float g_attn[B][D];
__device__ __align__(16) float g_out_part[NSPLIT1][B][D];

__device__ __forceinline__ void cp16(unsigned dst, const void* src) {
    asm volatile("cp.async.cg.shared.global [%0], [%1], 16;" :: "r"(dst), "l"(src));
}
#define CP_COMMIT() asm volatile("cp.async.commit_group;")
#define CP_WAIT1()  asm volatile("cp.async.wait_group 1;")

// ---------------- kernel 1: QKV projection (split-K GEMV) ----------------
__global__ __launch_bounds__(256) void proj_qkv(const float* __restrict__ x,
                         const float* __restrict__ wq,
                         const float* __restrict__ wk, const float* __restrict__ wv) {
    __shared__ float xs[B][ICHUNK];
    const int tid = threadIdx.x;
    const int j = blockIdx.x * 256 + tid;
    const int i0 = blockIdx.y * ICHUNK;

    for (int idx = tid; idx < B * ICHUNK; idx += 256) {
        int b = idx / ICHUNK, ii = idx % ICHUNK;
        xs[b][ii] = x[b * D + i0 + ii];
    }
    __syncthreads();

    const float* w; int stride, jl;
    if (j < H*HD)                 { w = wq; stride = H*HD;  jl = j; }
    else if (j < H*HD + KVH*HD)   { w = wk; stride = KVH*HD; jl = j - H*HD; }
    else                          { w = wv; stride = KVH*HD; jl = j - H*HD - KVH*HD; }
    const float* wp = w + (size_t)i0 * stride + jl;

    float acc[B];
    #pragma unroll
    for (int b = 0; b < B; b++) acc[b] = 0.f;

    #pragma unroll 8
    for (int ii = 0; ii < ICHUNK; ii++) {
        float wvv = wp[(size_t)ii * stride];
        #pragma unroll
        for (int b = 0; b < B; b++) acc[b] = fmaf(xs[b][ii], wvv, acc[b]);
    }
    #pragma unroll
    for (int b = 0; b < B; b++) g_qkv_part[blockIdx.y][b][j] = acc[b];
}

// ---------------- kernel 2: reduce partials + RoPE + scatter ----------------
__global__ void rope_scatter(const float* __restrict__ fcos, const float* __restrict__ fsin) {
    const int t = blockIdx.x * 128 + threadIdx.x;
    const int b  = t / (NCOLS / 2);
    const int pj = t % (NCOLS / 2);
    const int j0 = 2 * pj;

    float v0 = 0.f, v1 = 0.f;
    #pragma unroll
    for (int s = 0; s < NSPLIT1; s++) {
        v0 += g_qkv_part[s][b][j0];
        v1 += g_qkv_part[s][b][j0 + 1];
    }

    if (j0 < H*HD) {                                      // q + RoPE, pre-scaled
        int p = (j0 & (HD-1)) >> 1;
        float c = fcos[p] * SCALE, s_ = fsin[p] * SCALE;
        g_q[b][j0]     = v0 * c - v1 * s_;
        g_q[b][j0 + 1] = v0 * s_ + v1 * c;
    } else if (j0 < H*HD + KVH*HD) {                      // k + RoPE
        int l = j0 - H*HD; int kvh = l >> 7; int d = l & (HD-1); int p = d >> 1;
        float c = fcos[p], s_ = fsin[p];
        g_knew[b][kvh][d]     = v0 * c - v1 * s_;
        g_knew[b][kvh][d + 1] = v0 * s_ + v1 * c;
    } else {                                              // v
        int l = j0 - H*HD - KVH*HD; int kvh = l >> 7; int d = l & (HD-1);
        g_vnew[b][kvh][d]     = v0;
        g_vnew[b][kvh][d + 1] = v1;
    }
}

// ---------------- kernel 3: pipelined flash-decode attention + cache emit ----------------
__global__ __launch_bounds__(256, 3) void attn_pass1(
        const float* __restrict__ cache_k, const float* __restrict__ cache_v,
        const float* __restrict__ mask, const int* __restrict__ pos_p,
        float* __restrict__ out_k, float* __restrict__ out_v) {
    extern __shared__ float sm[];
    float*  Qs  = sm + SM_Q;
    float*  sc  = sm + SM_SC;
    float*  ps  = sm + SM_PS;
    float*  rmx = sm + SM_RMX;
    float*  rsm = sm + SM_RSM;
    float*  cr  = sm + SM_CR;

    const int bx = blockIdx.x;
    const int split = bx % MSPLIT;
    const int kvh = (bx / MSPLIT) % KVH;
    const int b = bx / (MSPLIT * KVH);
    const int tid = threadIdx.x;
    const int pos = pos_p[0];

    const size_t base = (size_t)(b * KVH + kvh) * M * HD;
    const float4* Kg = (const float4*)(cache_k + base);
    const float4* Vg = (const float4*)(cache_v + base);
    float4* Kog = (float4*)(out_k + base);
    float4* Vog = (float4*)(out_v + base);
    const float4* knew4 = (const float4*)&g_knew[b][kvh][0];
    const float4* vnew4 = (const float4*)&g_vnew[b][kvh][0];

    const int m_start = split * MC;

    // issue tile 0 into buffer 0 (4 K + 4 V f4 per thread)
    {
        float4* Kb = (float4*)sm;
        float4* Vb = (float4*)sm + 32*33;
        const int fb = m_start * 32;
        #pragma unroll
        for (int i = 0; i < 4; i++) {
            int ff = tid + i * 256; int row = ff >> 5, c4 = ff & 31;
            cp16((unsigned)__cvta_generic_to_shared(&Kb[row*33 + c4]), &Kg[fb + ff]);
        }
        #pragma unroll
        for (int i = 0; i < 4; i++) {
            int ff = tid + i * 256; int row = ff >> 5, c4 = ff & 31;
            cp16((unsigned)__cvta_generic_to_shared(&Vb[row*33 + c4]), &Vg[fb + ff]);
        }
        CP_COMMIT();
    }

    // init while tile 0 is in flight
    if (tid < 4) { rmx[tid] = -1e30f; rsm[tid] = 0.f; }
    #pragma unroll
    for (int i = 0; i < 2; i++)
        Qs[tid + i * 256] = g_q[b][kvh * NREP * HD + tid + i * 256];

    // per-thread roles
    const int r  = tid >> 2;          // score row   (tid < 128)
    const int h  = tid & 3;           // score head
    const int d  = tid & 127;         // accum dim
    const int hp = tid >> 7;          // accum head-pair
    const int h0 = hp * 2, h1 = h0 + 1;
    const int et = tid - 128;         // emit thread (tid >= 128)
    const float* maskp = mask + ((size_t)(b * H) + kvh * NREP + h) * M;

    float o0 = 0.f, o1 = 0.f;

    for (int t = 0; t < NT; t++) {
        const int p = t & 1;
        float4* Kb = (float4*)sm + p * (BUF_F/4);
        float4* Vb = Kb + 32*33;
        const int m0 = m_start + t * TILE;

        // issue tile t+1 into other buffer
        if (t + 1 < NT) {
            float4* Kn = (float4*)sm + ((t+1) & 1) * (BUF_F/4);
            float4* Vn = Kn + 32*33;
            const int fbn = (m0 + TILE) * 32;
            #pragma unroll
            for (int i = 0; i < 4; i++) {
                int ff = tid + i * 256; int row = ff >> 5, c4 = ff & 31;
                cp16((unsigned)__cvta_generic_to_shared(&Kn[row*33 + c4]), &Kg[fbn + ff]);
            }
            #pragma unroll
            for (int i = 0; i < 4; i++) {
                int ff = tid + i * 256; int row = ff >> 5, c4 = ff & 31;
                cp16((unsigned)__cvta_generic_to_shared(&Vn[row*33 + c4]), &Vg[fbn + ff]);
            }
        }
        CP_COMMIT();
        CP_WAIT1();            // tile t arrived
        __syncthreads();

        // patch pos row (block-uniform condition)
        if (pos >= m0 && pos < m0 + TILE) {
            const int pr = pos - m0;
            if (tid < 32)       Kb[pr*33 + tid] = knew4[tid];
            else if (tid < 64)  Vb[pr*33 + (tid-32)] = vnew4[tid-32];
            __syncthreads();
        }

        // scores (tid<128) || cache emit (tid>=128)
        if (tid < 128) {
            const float4* krow = Kb + r * 33;
            const float4* qrow = (const float4*)Qs + h * 32;
            float acc = 0.f;
            #pragma unroll
            for (int i = 0; i < 32; i++) {
                float4 k = krow[i];
                float4 q = qrow[i];
                acc = fmaf(k.x, q.x, acc);
                acc = fmaf(k.y, q.y, acc);
                acc = fmaf(k.z, q.z, acc);
                acc = fmaf(k.w, q.w, acc);
            }
            sc[tid] = acc + maskp[m0 + r];
        } else {
            const int fb = m0 * 32;
            #pragma unroll
            for (int i = 0; i < 8; i++) {
                int ff = et + i * 128; int row = ff >> 5, c4 = ff & 31;
                Kog[fb + ff] = Kb[row*33 + c4];
            }
            #pragma unroll
            for (int i = 0; i < 8; i++) {
                int ff = et + i * 128; int row = ff >> 5, c4 = ff & 31;
                Vog[fb + ff] = Vb[row*33 + c4];
            }
        }
        __syncthreads();

        // tile max + running max/correction (warps 0-3, one head each)
        if (tid < 128) {
            int hh = tid >> 5, ln = tid & 31;
            float v = sc[ln * 4 + hh];
            #pragma unroll
            for (int off = 16; off; off >>= 1)
                v = fmaxf(v, __shfl_xor_sync(FULLMASK, v, off));
            if (ln == 0) {
                float nm = fmaxf(rmx[hh], v);
                cr[hh] = __expf(rmx[hh] - nm);
                rmx[hh] = nm;
            }
        }
        __syncthreads();

        // p = exp(s - max)
        if (tid < 128) ps[tid] = __expf(sc[tid] - rmx[h]);
        __syncthreads();

        // running sum (warps 0-3) — no dependency with accumulate below
        if (tid < 128) {
            int hh = tid >> 5, ln = tid & 31;
            float v = ps[ln * 4 + hh];
            #pragma unroll
            for (int off = 16; off; off >>= 1)
                v += __shfl_xor_sync(FULLMASK, v, off);
            if (ln == 0) rsm[hh] = rsm[hh] * cr[hh] + v;
        }
        // accumulate: 2 heads per thread at dim d
        {
            const float* Vf = (const float*)Vb;
            o0 *= cr[h0];
            o1 *= cr[h1];
            #pragma unroll 4
            for (int m = 0; m < TILE; m++) {
                float vv = Vf[m * 132 + d];
                o0 = fmaf(ps[m * 4 + h0], vv, o0);
                o1 = fmaf(ps[m * 4 + h1], vv, o1);
            }
        }
        __syncthreads();   // protect buffer t from prefetch overwrite at t+1
    }

    g_part_o[b][kvh][split][h0][d] = o0;
    g_part_o[b][kvh][split][h1][d] = o1;
    if (tid < 4) {
        g_part_m[b][kvh][split][tid] = rmx[tid];
        g_part_l[b][kvh][split][tid] = rsm[tid];
    }
}

// ---------------- kernel 4: combine m-splits (one block per b,kvh,h) ----------------
__global__ void attn_reduce() {
    const int bx = blockIdx.x;
    const int h = bx & 3;
    const int kvh = (bx >> 2) & 7;
    const int b = bx >> 5;
    const int d = threadIdx.x;

    float Mx = -1e30f;
    #pragma unroll
    for (int s = 0; s < MSPLIT; s++) Mx = fmaxf(Mx, g_part_m[b][kvh][s][h]);
    float L = 0.f, O = 0.f;
    #pragma unroll
    for (int s = 0; s < MSPLIT; s++) {
        float e = __expf(g_part_m[b][kvh][s][h] - Mx);
        L += g_part_l[b][kvh][s][h] * e;
        O += g_part_o[b][kvh][s][h][d] * e;
    }
    g_attn[b][(kvh * NREP + h) * HD + d] = O / L;
}

// ---------------- kernel 5: output projection (split-K GEMV) ----------------
__global__ __launch_bounds__(256) void oproj(const float* __restrict__ wo) {
    __shared__ float xs[B][ICHUNK];
    const int tid = threadIdx.x;
    const int j = blockIdx.x * 256 + tid;
    const int i0 = blockIdx.y * ICHUNK;

    for (int idx = tid; idx < B * ICHUNK; idx += 256) {
        int b = idx / ICHUNK, ii = idx % ICHUNK;
        xs[b][ii] = g_attn[b][i0 + ii];
    }
    __syncthreads();

    const float* wp = wo + (size_t)i0 * D + j;
    float acc[B];
    #pragma unroll
    for (int b = 0; b < B; b++) acc[b] = 0.f;
    #pragma unroll 8
    for (int ii = 0; ii < ICHUNK; ii++) {
        float wvv = wp[(size_t)ii * D];
        #pragma unroll
        for (int b = 0; b < B; b++) acc[b] = fmaf(xs[b][ii], wvv, acc[b]);
    }
    #pragma unroll
    for (int b = 0; b < B; b++) g_out_part[blockIdx.y][b][j] = acc[b];
}

// ---------------- kernel 6: final reduce -> d_out ----------------
__global__ void oproj_reduce(float* __restrict__ out) {
    const int t = blockIdx.x * 128 + threadIdx.x;
    const int b = t / D, j = t % D;
    float a = 0.f;
    #pragma unroll
    for (int s = 0; s < NSPLIT1; s++) a += g_out_part[s][b][j];
    out[(size_t)b * D + j] = a;
}

// ---------------- launch ----------------
extern "C" void kernel_launch(void* const* d_in, const int* in_sizes, int n_in,
                              void* d_out, int out_size) {
    const float* x        = (const float*)d_in[0];
    const float* fcos     = (const float*)d_in[1];
    const float* fsin     = (const float*)d_in[2];
    const float* mask     = (const float*)d_in[3];
    const float* cache_k  = (const float*)d_in[4];
    const float* cache_v  = (const float*)d_in[5];
    const int*   in_idx   = (const int*)d_in[7];
    const float* wq       = (const float*)d_in[9];
    const float* wk       = (const float*)d_in[10];
    const float* wv       = (const float*)d_in[11];
    const float* wo       = (const float*)d_in[12];

    float* out   = (float*)d_out;
    float* out_k = out + (size_t)B * D;
    float* out_v = out_k + (size_t)B * KVH * M * HD;

    cudaFuncSetAttribute(attn_pass1, cudaFuncAttributeMaxDynamicSharedMemorySize, SMEM_BYTES);

    proj_qkv<<<dim3(NCOLS / 256, NSPLIT1), 256>>>(x, wq, wk, wv);
    rope_scatter<<<(B * NCOLS / 2) / 128, 128>>>(fcos, fsin);
    attn_pass1<<<B * KVH * MSPLIT, 256, SMEM_BYTES>>>(cache_k, cache_v, mask, in_idx, out_k, out_v);
    attn_reduce<<<B * KVH * NREP, 128>>>();
    oproj<<<dim3(D / 256, NSPLIT1), 256>>>(wo);
    oproj_reduce<<<(B * D) / 128, 128>>>(out);
}

// round 6
// speedup vs baseline: 2.4660x; 1.0982x over previous
#include <cuda_runtime.h>
#include <math.h>

#define B 8
#define D 4096
#define H 32
#define KVH 8
#define HD 128
#define M 4096
#define NREP 4
#define NCOLS (H*HD + 2*KVH*HD)   /* 6144 */
#define NSPLIT1 64
#define ICH1 (D/NSPLIT1)          /* 64 */
#define NSPLIT2 64
#define ICH2 (D/NSPLIT2)          /* 64 */
#define MSPLIT 32
#define MC (M/MSPLIT)             /* 128 */
#define TILE 32
#define NT (MC/TILE)              /* 4 */
#define SCALE 0.08838834764831845f
#define FULLMASK 0xffffffffu

// attn smem (floats): two tile buffers (32 rows x 33 float4), Q, scores
#define TB_F (32*33*4)            /* 4224 floats per tile buffer */
#define SM_Q  (2*TB_F)            /* 8448 */
#define SM_SC (SM_Q+512)          /* 8960: sc[128][4] */
#define SM_FLOATS (SM_SC+512)     /* 9472 -> 37888 B */

// ---------------- static device scratch ----------------
__device__ __align__(16) float g_qkv_part[NSPLIT1][B][NCOLS];
__device__ __align__(16) float g_q[B][H*HD];
__device__ __align__(16) float g_knew[B][KVH][HD];
__device__ __align__(16) float g_vnew[B][KVH][HD];
__device__ __align__(16) float g_part_o[B][KVH][MSPLIT][NREP][HD];
__device__ float g_part_m[B][KVH][MSPLIT][NREP];
__device__ float g_part_l[B][KVH][MSPLIT][NREP];
__device__ __align__(16) float g_out_part[NSPLIT2][B][D];

__device__ __forceinline__ void cp16(void* dst, const void* src) {
    unsigned u = (unsigned)__cvta_generic_to_shared(dst);
    asm volatile("cp.async.cg.shared.global [%0], [%1], 16;" :: "r"(u), "l"(src));
}
#define CP_COMMIT() asm volatile("cp.async.commit_group;")
#define CP_WAIT0()  asm volatile("cp.async.wait_group 0;" ::: "memory")

// ---------------- kernel 1: QKV projection (split-K GEMV, float4 columns) ----------------
__global__ __launch_bounds__(256) void proj_qkv(const float* __restrict__ x,
                         const float* __restrict__ wq,
                         const float* __restrict__ wk, const float* __restrict__ wv) {
    __shared__ float xs[B][ICH1];
    const int tid = threadIdx.x;
    const int j4 = blockIdx.x * 256 + tid;       // float4 column index (0..1535)
    const int j = 4 * j4;
    const int i0 = blockIdx.y * ICH1;

    for (int idx = tid; idx < B * ICH1; idx += 256) {
        int b = idx / ICH1, ii = idx % ICH1;
        xs[b][ii] = x[b * D + i0 + ii];
    }
    __syncthreads();

    const float* w; int stride, jl;
    if (j < H*HD)                 { w = wq; stride = H*HD;  jl = j; }
    else if (j < H*HD + KVH*HD)   { w = wk; stride = KVH*HD; jl = j - H*HD; }
    else                          { w = wv; stride = KVH*HD; jl = j - H*HD - KVH*HD; }
    const float* wp = w + (size_t)i0 * stride + jl;

    float4 acc[B];
    #pragma unroll
    for (int b = 0; b < B; b++) acc[b] = make_float4(0.f,0.f,0.f,0.f);

    #pragma unroll 4
    for (int ii = 0; ii < ICH1; ii++) {
        float4 w4 = *(const float4*)(wp + (size_t)ii * stride);
        #pragma unroll
        for (int b = 0; b < B; b++) {
            float xv = xs[b][ii];
            acc[b].x = fmaf(xv, w4.x, acc[b].x);
            acc[b].y = fmaf(xv, w4.y, acc[b].y);
            acc[b].z = fmaf(xv, w4.z, acc[b].z);
            acc[b].w = fmaf(xv, w4.w, acc[b].w);
        }
    }
    #pragma unroll
    for (int b = 0; b < B; b++)
        *(float4*)&g_qkv_part[blockIdx.y][b][j] = acc[b];
}

// ---------------- kernel 2: reduce partials + RoPE + scatter ----------------
__global__ void rope_scatter(const float* __restrict__ fcos, const float* __restrict__ fsin) {
    const int t = blockIdx.x * 128 + threadIdx.x;
    const int b  = t / (NCOLS / 2);
    const int pj = t % (NCOLS / 2);
    const int j0 = 2 * pj;

    float v0 = 0.f, v1 = 0.f;
    #pragma unroll
    for (int s = 0; s < NSPLIT1; s++) {
        float2 p = *(const float2*)&g_qkv_part[s][b][j0];
        v0 += p.x; v1 += p.y;
    }

    if (j0 < H*HD) {                                      // q + RoPE, pre-scaled
        int p = (j0 & (HD-1)) >> 1;
        float c = fcos[p] * SCALE, s_ = fsin[p] * SCALE;
        g_q[b][j0]     = v0 * c - v1 * s_;
        g_q[b][j0 + 1] = v0 * s_ + v1 * c;
    } else if (j0 < H*HD + KVH*HD) {                      // k + RoPE
        int l = j0 - H*HD; int kvh = l >> 7; int d = l & (HD-1); int p = d >> 1;
        float c = fcos[p], s_ = fsin[p];
        g_knew[b][kvh][d]     = v0 * c - v1 * s_;
        g_knew[b][kvh][d + 1] = v0 * s_ + v1 * c;
    } else {                                              // v
        int l = j0 - H*HD - KVH*HD; int kvh = l >> 7; int d = l & (HD-1);
        g_vnew[b][kvh][d]     = v0;
        g_vnew[b][kvh][d + 1] = v1;
    }
}

// ---------------- kernel 3: two-phase flash-decode attention + cache emit ----------------
__global__ __launch_bounds__(256, 4) void attn_pass1(
        const float* __restrict__ cache_k, const float* __restrict__ cache_v,
        const float* __restrict__ mask, const int* __restrict__ pos_p,
        float* __restrict__ out_k, float* __restrict__ out_v) {
    __shared__ float sm[SM_FLOATS];
    float* Qs = sm + SM_Q;
    float* sc = sm + SM_SC;

    const int bx = blockIdx.x;
    const int split = bx % MSPLIT;
    const int kvh = (bx / MSPLIT) % KVH;
    const int b = bx / (MSPLIT * KVH);
    const int tid = threadIdx.x;
    const int pos = pos_p[0];

    const size_t base = (size_t)(b * KVH + kvh) * M * HD;
    const float4* Kg = (const float4*)(cache_k + base);
    const float4* Vg = (const float4*)(cache_v + base);
    float4* Kog = (float4*)(out_k + base);
    float4* Vog = (float4*)(out_v + base);
    const float4* knew4 = (const float4*)&g_knew[b][kvh][0];
    const float4* vnew4 = (const float4*)&g_vnew[b][kvh][0];

    const int m_start = split * MC;

    // issue K tile 0 into buffer 0
    {
        float4* Kb = (float4*)sm;
        const int fb = m_start * 32;
        #pragma unroll
        for (int i = 0; i < 4; i++) {
            int ff = tid + i * 256, row = ff >> 5, c4 = ff & 31;
            cp16(&Kb[row*33 + c4], &Kg[fb + ff]);
        }
        CP_COMMIT();
    }

    // load Q while tile 0 in flight
    #pragma unroll
    for (int i = 0; i < 2; i++)
        Qs[tid + i * 256] = g_q[b][kvh * NREP * HD + tid + i * 256];

    const int r = tid >> 2;           // score row (tid<128)
    const int h = tid & 3;            // score head
    const int d = tid & 127;          // accum dim
    const int h0 = (tid >> 7) * 2, h1 = h0 + 1;
    const float* maskp = mask + ((size_t)(b * H) + kvh * NREP + h) * M;

    // ---------------- phase 1: K tiles -> scores + K emit ----------------
    // K tile t lives in buffer (t&1). Last prefetch: V tile 0 -> buffer (NT&1)=0.
    for (int t = 0; t < NT; t++) {
        float4* Sb = (float4*)sm + (t & 1) * (TB_F/4);
        const int m0 = m_start + t * TILE;

        CP_WAIT0();            // tile t arrived (this thread's copies)
        __syncthreads();       // all threads' copies done + all reads of other buffer done

        // safe to prefetch into the other buffer now
        if (t + 1 < NT) {
            float4* Nb = (float4*)sm + ((t+1) & 1) * (TB_F/4);
            const int fbn = (m0 + TILE) * 32;
            #pragma unroll
            for (int i = 0; i < 4; i++) {
                int ff = tid + i * 256, row = ff >> 5, c4 = ff & 31;
                cp16(&Nb[row*33 + c4], &Kg[fbn + ff]);
            }
        } else {
            float4* Nb = (float4*)sm + ((t+1) & 1) * (TB_F/4);  // V tile 0 -> buf 0
            const int fbn = m_start * 32;
            #pragma unroll
            for (int i = 0; i < 4; i++) {
                int ff = tid + i * 256, row = ff >> 5, c4 = ff & 31;
                cp16(&Nb[row*33 + c4], &Vg[fbn + ff]);
            }
        }
        CP_COMMIT();

        if (pos >= m0 && pos < m0 + TILE) {      // patch new K row (block-uniform)
            if (tid < 32) Sb[(pos - m0)*33 + tid] = knew4[tid];
            __syncthreads();
        }

        if (tid < 128) {                          // scores
            const float4* krow = Sb + r * 33;
            const float4* qrow = (const float4*)Qs + h * 32;
            float acc = 0.f;
            #pragma unroll
            for (int i = 0; i < 32; i++) {
                float4 k = krow[i], q = qrow[i];
                acc = fmaf(k.x, q.x, acc);
                acc = fmaf(k.y, q.y, acc);
                acc = fmaf(k.z, q.z, acc);
                acc = fmaf(k.w, q.w, acc);
            }
            sc[(t * TILE + r) * 4 + h] = acc + maskp[m0 + r];
        } else {                                  // emit K
            const int et = tid - 128;
            const int fb = m0 * 32;
            #pragma unroll
            for (int i = 0; i < 8; i++) {
                int ff = et + i * 128, row = ff >> 5, c4 = ff & 31;
                Kog[fb + ff] = Sb[row*33 + c4];
            }
        }
    }
    __syncthreads();

    // ---------------- phase 2: one softmax over all 128 rows (warps 0-3) ----------------
    if (tid < 128) {
        const int w = tid >> 5, ln = tid & 31;
        float s0 = sc[(ln      ) * 4 + w];
        float s1 = sc[(ln + 32 ) * 4 + w];
        float s2 = sc[(ln + 64 ) * 4 + w];
        float s3 = sc[(ln + 96 ) * 4 + w];
        float v = fmaxf(fmaxf(s0, s1), fmaxf(s2, s3));
        #pragma unroll
        for (int off = 16; off; off >>= 1)
            v = fmaxf(v, __shfl_xor_sync(FULLMASK, v, off));
        float e0 = __expf(s0 - v), e1 = __expf(s1 - v);
        float e2 = __expf(s2 - v), e3 = __expf(s3 - v);
        sc[(ln      ) * 4 + w] = e0;
        sc[(ln + 32 ) * 4 + w] = e1;
        sc[(ln + 64 ) * 4 + w] = e2;
        sc[(ln + 96 ) * 4 + w] = e3;
        float l = e0 + e1 + e2 + e3;
        #pragma unroll
        for (int off = 16; off; off >>= 1)
            l += __shfl_xor_sync(FULLMASK, l, off);
        if (ln == 0) {
            g_part_m[b][kvh][split][w] = v;
            g_part_l[b][kvh][split][w] = l;
        }
    }
    __syncthreads();

    // ---------------- phase 3: V tiles -> accumulate + V emit ----------------
    // V tile t lives in buffer (t&1)  [V0 was prefetched into buffer 0 above]
    float o0 = 0.f, o1 = 0.f;
    for (int t = 0; t < NT; t++) {
        float4* Sb = (float4*)sm + (t & 1) * (TB_F/4);
        const int m0 = m_start + t * TILE;

        CP_WAIT0();            // V tile t arrived
        __syncthreads();       // all copies visible + prior reads of other buffer done

        if (t + 1 < NT) {      // prefetch V(t+1) into the other buffer
            float4* Nb = (float4*)sm + ((t+1) & 1) * (TB_F/4);
            const int fbn = (m0 + TILE) * 32;
            #pragma unroll
            for (int i = 0; i < 4; i++) {
                int ff = tid + i * 256, row = ff >> 5, c4 = ff & 31;
                cp16(&Nb[row*33 + c4], &Vg[fbn + ff]);
            }
            CP_COMMIT();
        }

        if (pos >= m0 && pos < m0 + TILE) {      // patch new V row
            if (tid < 32) Sb[(pos - m0)*33 + tid] = vnew4[tid];
            __syncthreads();
        }

        const float* Vf = (const float*)Sb;
        #pragma unroll 4
        for (int m = 0; m < TILE; m++) {
            float vv = Vf[m * 132 + d];
            int gr = t * TILE + m;
            o0 = fmaf(sc[gr * 4 + h0], vv, o0);
            o1 = fmaf(sc[gr * 4 + h1], vv, o1);
        }
        {   // emit V (all 256 threads, 4 f4 each)
            const int fb = m0 * 32;
            #pragma unroll
            for (int i = 0; i < 4; i++) {
                int ff = tid + i * 256, row = ff >> 5, c4 = ff & 31;
                Vog[fb + ff] = Sb[row*33 + c4];
            }
        }
    }

    g_part_o[b][kvh][split][h0][d] = o0;
    g_part_o[b][kvh][split][h1][d] = o1;
}

// ---------------- kernel 4: output projection (fused attn combine + split-K GEMV) ----------------
__global__ __launch_bounds__(256) void oproj(const float* __restrict__ wo) {
    __shared__ float xs[B][ICH2];
    const int tid = threadIdx.x;
    const int i0 = blockIdx.y * ICH2;

    // prologue: reconstruct attention output slice from split partials
    for (int e = tid; e < B * ICH2; e += 256) {
        int bb = e >> 6, ii = e & 63;
        int jc = i0 + ii;
        int kvh = jc >> 9, hh = (jc >> 7) & 3, dd = jc & 127;
        float Mx = -1e30f;
        #pragma unroll
        for (int s = 0; s < MSPLIT; s++) Mx = fmaxf(Mx, g_part_m[bb][kvh][s][hh]);
        float L = 0.f, O = 0.f;
        #pragma unroll
        for (int s = 0; s < MSPLIT; s++) {
            float ee = __expf(g_part_m[bb][kvh][s][hh] - Mx);
            L += g_part_l[bb][kvh][s][hh] * ee;
            O += g_part_o[bb][kvh][s][hh][dd] * ee;
        }
        xs[bb][ii] = O / L;
    }
    __syncthreads();

    const int j2 = blockIdx.x * 256 + tid;       // float2 column (0..2047)
    const int j = 2 * j2;
    const float* wp = wo + (size_t)i0 * D + j;

    float2 acc[B];
    #pragma unroll
    for (int b = 0; b < B; b++) acc[b] = make_float2(0.f, 0.f);

    #pragma unroll 4
    for (int ii = 0; ii < ICH2; ii++) {
        float2 w2 = *(const float2*)(wp + (size_t)ii * D);
        #pragma unroll
        for (int b = 0; b < B; b++) {
            float xv = xs[b][ii];
            acc[b].x = fmaf(xv, w2.x, acc[b].x);
            acc[b].y = fmaf(xv, w2.y, acc[b].y);
        }
    }
    #pragma unroll
    for (int b = 0; b < B; b++)
        *(float2*)&g_out_part[blockIdx.y][b][j] = acc[b];
}

// ---------------- kernel 5: final reduce -> d_out ----------------
__global__ void oproj_reduce(float* __restrict__ out) {
    const int t = blockIdx.x * 256 + threadIdx.x;
    const int b = t / D, j = t % D;
    float a = 0.f;
    #pragma unroll
    for (int s = 0; s < NSPLIT2; s++) a += g_out_part[s][b][j];
    out[(size_t)b * D + j] = a;
}

// ---------------- launch ----------------
extern "C" void kernel_launch(void* const* d_in, const int* in_sizes, int n_in,
                              void* d_out, int out_size) {
    const float* x        = (const float*)d_in[0];
    const float* fcos     = (const float*)d_in[1];
    const float* fsin     = (const float*)d_in[2];
    const float* mask     = (const float*)d_in[3];
    const float* cache_k  = (const float*)d_in[4];
    const float* cache_v  = (const float*)d_in[5];
    const int*   in_idx   = (const int*)d_in[7];
    const float* wq       = (const float*)d_in[9];
    const float* wk       = (const float*)d_in[10];
    const float* wv       = (const float*)d_in[11];
    const float* wo       = (const float*)d_in[12];

    float* out   = (float*)d_out;
    float* out_k = out + (size_t)B * D;
    float* out_v = out_k + (size_t)B * KVH * M * HD;

    proj_qkv<<<dim3(NCOLS / 1024, NSPLIT1), 256>>>(x, wq, wk, wv);
    rope_scatter<<<(B * NCOLS / 2) / 128, 128>>>(fcos, fsin);
    attn_pass1<<<B * KVH * MSPLIT, 256>>>(cache_k, cache_v, mask, in_idx, out_k, out_v);
    oproj<<<dim3(D / 512, NSPLIT2), 256>>>(wo);
    oproj_reduce<<<(B * D) / 256, 256>>>(out);
}

// round 7
// speedup vs baseline: 2.6029x; 1.0555x over previous
#include <cuda_runtime.h>
#include <math.h>

#define B 8
#define D 4096
#define H 32
#define KVH 8
#define HD 128
#define M 4096
#define NREP 4
#define NCOLS (H*HD + 2*KVH*HD)   /* 6144 */
#define NSPLIT1 64
#define ICH1 (D/NSPLIT1)          /* 64 */
#define NSPLIT2 64
#define ICH2 (D/NSPLIT2)          /* 64 */
#define MSPLIT 32
#define MC (M/MSPLIT)             /* 128 */
#define TILE 32
#define NT (MC/TILE)              /* 4 */
#define NU (2*NT)                 /* 8 unified tiles: 4 K then 4 V */
#define SCALE 0.08838834764831845f
#define FULLMASK 0xffffffffu

// attn smem (floats): THREE tile buffers (32 rows x 33 float4), Q, scores
#define TB_F (32*33*4)            /* 4224 floats per tile buffer */
#define SM_Q  (3*TB_F)            /* 12672 */
#define SM_SC (SM_Q+512)          /* 13184: sc[128][4] */
#define SM_FLOATS (SM_SC+512)     /* 13696 -> 54784 B */
#define SMEM_BYTES (SM_FLOATS*4)

// ---------------- static device scratch ----------------
__device__ __align__(16) float g_qkv_part[NSPLIT1][B][NCOLS];
__device__ __align__(16) float g_q[B][H*HD];
__device__ __align__(16) float g_knew[B][KVH][HD];
__device__ __align__(16) float g_vnew[B][KVH][HD];
__device__ __align__(16) float g_part_o[B][KVH][MSPLIT][NREP][HD];
__device__ float g_part_m[B][KVH][MSPLIT][NREP];
__device__ float g_part_l[B][KVH][MSPLIT][NREP];
__device__ __align__(16) float g_out_part[NSPLIT2][B][D];

__device__ __forceinline__ void cp16(void* dst, const void* src) {
    unsigned u = (unsigned)__cvta_generic_to_shared(dst);
    asm volatile("cp.async.cg.shared.global [%0], [%1], 16;" :: "r"(u), "l"(src));
}
#define CP_COMMIT() asm volatile("cp.async.commit_group;")
#define CP_WAIT1()  asm volatile("cp.async.wait_group 1;" ::: "memory")

// ---------------- kernel 1: QKV projection (split-K GEMV, float4 columns) ----------------
__global__ __launch_bounds__(256) void proj_qkv(const float* __restrict__ x,
                         const float* __restrict__ wq,
                         const float* __restrict__ wk, const float* __restrict__ wv) {
    __shared__ float xs[B][ICH1];
    const int tid = threadIdx.x;
    const int j4 = blockIdx.x * 256 + tid;       // float4 column index (0..1535)
    const int j = 4 * j4;
    const int i0 = blockIdx.y * ICH1;

    for (int idx = tid; idx < B * ICH1; idx += 256) {
        int b = idx / ICH1, ii = idx % ICH1;
        xs[b][ii] = x[b * D + i0 + ii];
    }
    __syncthreads();

    const float* w; int stride, jl;
    if (j < H*HD)                 { w = wq; stride = H*HD;  jl = j; }
    else if (j < H*HD + KVH*HD)   { w = wk; stride = KVH*HD; jl = j - H*HD; }
    else                          { w = wv; stride = KVH*HD; jl = j - H*HD - KVH*HD; }
    const float* wp = w + (size_t)i0 * stride + jl;

    float4 acc[B];
    #pragma unroll
    for (int b = 0; b < B; b++) acc[b] = make_float4(0.f,0.f,0.f,0.f);

    #pragma unroll 4
    for (int ii = 0; ii < ICH1; ii++) {
        float4 w4 = *(const float4*)(wp + (size_t)ii * stride);
        #pragma unroll
        for (int b = 0; b < B; b++) {
            float xv = xs[b][ii];
            acc[b].x = fmaf(xv, w4.x, acc[b].x);
            acc[b].y = fmaf(xv, w4.y, acc[b].y);
            acc[b].z = fmaf(xv, w4.z, acc[b].z);
            acc[b].w = fmaf(xv, w4.w, acc[b].w);
        }
    }
    #pragma unroll
    for (int b = 0; b < B; b++)
        *(float4*)&g_qkv_part[blockIdx.y][b][j] = acc[b];
}

// ---------------- kernel 2: reduce partials + RoPE + scatter ----------------
__global__ void rope_scatter(const float* __restrict__ fcos, const float* __restrict__ fsin) {
    const int t = blockIdx.x * 128 + threadIdx.x;
    const int b  = t / (NCOLS / 2);
    const int pj = t % (NCOLS / 2);
    const int j0 = 2 * pj;

    float v0 = 0.f, v1 = 0.f;
    #pragma unroll
    for (int s = 0; s < NSPLIT1; s++) {
        float2 p = *(const float2*)&g_qkv_part[s][b][j0];
        v0 += p.x; v1 += p.y;
    }

    if (j0 < H*HD) {                                      // q + RoPE, pre-scaled
        int p = (j0 & (HD-1)) >> 1;
        float c = fcos[p] * SCALE, s_ = fsin[p] * SCALE;
        g_q[b][j0]     = v0 * c - v1 * s_;
        g_q[b][j0 + 1] = v0 * s_ + v1 * c;
    } else if (j0 < H*HD + KVH*HD) {                      // k + RoPE
        int l = j0 - H*HD; int kvh = l >> 7; int d = l & (HD-1); int p = d >> 1;
        float c = fcos[p], s_ = fsin[p];
        g_knew[b][kvh][d]     = v0 * c - v1 * s_;
        g_knew[b][kvh][d + 1] = v0 * s_ + v1 * c;
    } else {                                              // v
        int l = j0 - H*HD - KVH*HD; int kvh = l >> 7; int d = l & (HD-1);
        g_vnew[b][kvh][d]     = v0;
        g_vnew[b][kvh][d + 1] = v1;
    }
}

// ---------------- kernel 3: 3-stage-pipelined flash-decode attention + cache emit ----------------
// Unified tile index u in [0, 2*NT): u < NT -> K tile u; u >= NT -> V tile u-NT.
// Tile u lives in buffer u%3. Invariant: at top of iter u, groups for tiles <= u+1
// are committed and wait_group 1 guarantees tile u's group is complete.
__device__ __forceinline__ void issue_tile(float* sm, int u, int tid, int m_start,
                                           const float4* Kg, const float4* Vg) {
    const float4* src = (u < NT) ? Kg : Vg;
    const int mt = (u < NT) ? u : u - NT;
    const int fb = (m_start + mt * TILE) * 32;
    float4* Nb = (float4*)sm + (u % 3) * (TB_F/4);
    #pragma unroll
    for (int i = 0; i < 4; i++) {
        int ff = tid + i * 256, row = ff >> 5, c4 = ff & 31;
        cp16(&Nb[row*33 + c4], &src[fb + ff]);
    }
}

__global__ __launch_bounds__(256, 4) void attn_pass1(
        const float* __restrict__ cache_k, const float* __restrict__ cache_v,
        const float* __restrict__ mask, const int* __restrict__ pos_p,
        float* __restrict__ out_k, float* __restrict__ out_v) {
    extern __shared__ float sm[];
    float* Qs = sm + SM_Q;
    float* sc = sm + SM_SC;

    const int bx = blockIdx.x;
    const int split = bx % MSPLIT;
    const int kvh = (bx / MSPLIT) % KVH;
    const int b = bx / (MSPLIT * KVH);
    const int tid = threadIdx.x;
    const int pos = pos_p[0];

    const size_t base = (size_t)(b * KVH + kvh) * M * HD;
    const float4* Kg = (const float4*)(cache_k + base);
    const float4* Vg = (const float4*)(cache_v + base);
    float4* Kog = (float4*)(out_k + base);
    float4* Vog = (float4*)(out_v + base);
    const float4* knew4 = (const float4*)&g_knew[b][kvh][0];
    const float4* vnew4 = (const float4*)&g_vnew[b][kvh][0];

    const int m_start = split * MC;

    // prologue: issue tiles 0 and 1 as separate groups
    issue_tile(sm, 0, tid, m_start, Kg, Vg); CP_COMMIT();
    issue_tile(sm, 1, tid, m_start, Kg, Vg); CP_COMMIT();

    // load Q while tiles are in flight
    #pragma unroll
    for (int i = 0; i < 2; i++)
        Qs[tid + i * 256] = g_q[b][kvh * NREP * HD + tid + i * 256];

    const int r = tid >> 2;           // score row (tid<128)
    const int h = tid & 3;            // score head
    const int d = tid & 127;          // accum dim
    const int h0 = (tid >> 7) * 2, h1 = h0 + 1;
    const float* maskp = mask + ((size_t)(b * H) + kvh * NREP + h) * M;

    float o0 = 0.f, o1 = 0.f;

    for (int u = 0; u < NU; u++) {
        float4* Sb = (float4*)sm + (u % 3) * (TB_F/4);
        const bool isK = (u < NT);
        const int mt = isK ? u : u - NT;
        const int m0 = m_start + mt * TILE;

        CP_WAIT1();            // tile u's group complete (newest group may be pending)
        __syncthreads();       // copies visible to all + all reads of buf[(u+2)%3] done

        // softmax once at the K->V boundary (sc[] fully written by iters 0..NT-1)
        if (u == NT) {
            if (tid < 128) {
                const int w = tid >> 5, ln = tid & 31;
                float s0 = sc[(ln      ) * 4 + w];
                float s1 = sc[(ln + 32 ) * 4 + w];
                float s2 = sc[(ln + 64 ) * 4 + w];
                float s3 = sc[(ln + 96 ) * 4 + w];
                float v = fmaxf(fmaxf(s0, s1), fmaxf(s2, s3));
                #pragma unroll
                for (int off = 16; off; off >>= 1)
                    v = fmaxf(v, __shfl_xor_sync(FULLMASK, v, off));
                float e0 = __expf(s0 - v), e1 = __expf(s1 - v);
                float e2 = __expf(s2 - v), e3 = __expf(s3 - v);
                sc[(ln      ) * 4 + w] = e0;
                sc[(ln + 32 ) * 4 + w] = e1;
                sc[(ln + 64 ) * 4 + w] = e2;
                sc[(ln + 96 ) * 4 + w] = e3;
                float l = e0 + e1 + e2 + e3;
                #pragma unroll
                for (int off = 16; off; off >>= 1)
                    l += __shfl_xor_sync(FULLMASK, l, off);
                if (ln == 0) {
                    g_part_m[b][kvh][split][w] = v;
                    g_part_l[b][kvh][split][w] = l;
                }
            }
            __syncthreads();
        }

        // issue tile u+2 into buf[(u+2)%3] (safe: last read at iter u-1, before this sync)
        if (u + 2 < NU) issue_tile(sm, u + 2, tid, m_start, Kg, Vg);
        CP_COMMIT();           // always commit (possibly empty) to keep group count uniform

        // patch new-token row (block-uniform condition)
        if (pos >= m0 && pos < m0 + TILE) {
            const float4* nsrc = isK ? knew4 : vnew4;
            if (tid < 32) Sb[(pos - m0)*33 + tid] = nsrc[tid];
            __syncthreads();
        }

        if (isK) {
            if (tid < 128) {                      // scores
                const float4* krow = Sb + r * 33;
                const float4* qrow = (const float4*)Qs + h * 32;
                float acc = 0.f;
                #pragma unroll
                for (int i = 0; i < 32; i++) {
                    float4 k = krow[i], q = qrow[i];
                    acc = fmaf(k.x, q.x, acc);
                    acc = fmaf(k.y, q.y, acc);
                    acc = fmaf(k.z, q.z, acc);
                    acc = fmaf(k.w, q.w, acc);
                }
                sc[(mt * TILE + r) * 4 + h] = acc + maskp[m0 + r];
            } else {                              // emit K
                const int et = tid - 128;
                const int fb = m0 * 32;
                #pragma unroll
                for (int i = 0; i < 8; i++) {
                    int ff = et + i * 128, row = ff >> 5, c4 = ff & 31;
                    Kog[fb + ff] = Sb[row*33 + c4];
                }
            }
        } else {
            const float* Vf = (const float*)Sb;
            #pragma unroll 4
            for (int m = 0; m < TILE; m++) {
                float vv = Vf[m * 132 + d];
                int gr = mt * TILE + m;
                o0 = fmaf(sc[gr * 4 + h0], vv, o0);
                o1 = fmaf(sc[gr * 4 + h1], vv, o1);
            }
            {   // emit V (all 256 threads, 4 f4 each)
                const int fb = m0 * 32;
                #pragma unroll
                for (int i = 0; i < 4; i++) {
                    int ff = tid + i * 256, row = ff >> 5, c4 = ff & 31;
                    Vog[fb + ff] = Sb[row*33 + c4];
                }
            }
        }
    }

    g_part_o[b][kvh][split][h0][d] = o0;
    g_part_o[b][kvh][split][h1][d] = o1;
}

// ---------------- kernel 4: output projection (fused attn combine + split-K GEMV) ----------------
__global__ __launch_bounds__(256) void oproj(const float* __restrict__ wo) {
    __shared__ float xs[B][ICH2];
    const int tid = threadIdx.x;
    const int i0 = blockIdx.y * ICH2;

    // prologue: reconstruct attention output slice from split partials
    for (int e = tid; e < B * ICH2; e += 256) {
        int bb = e >> 6, ii = e & 63;
        int jc = i0 + ii;
        int kvh = jc >> 9, hh = (jc >> 7) & 3, dd = jc & 127;
        float Mx = -1e30f;
        #pragma unroll
        for (int s = 0; s < MSPLIT; s++) Mx = fmaxf(Mx, g_part_m[bb][kvh][s][hh]);
        float L = 0.f, O = 0.f;
        #pragma unroll
        for (int s = 0; s < MSPLIT; s++) {
            float ee = __expf(g_part_m[bb][kvh][s][hh] - Mx);
            L += g_part_l[bb][kvh][s][hh] * ee;
            O += g_part_o[bb][kvh][s][hh][dd] * ee;
        }
        xs[bb][ii] = O / L;
    }
    __syncthreads();

    const int j4 = blockIdx.x * 256 + tid;       // float4 column (0..1023)
    const int j = 4 * j4;
    const float* wp = wo + (size_t)i0 * D + j;

    float4 acc[B];
    #pragma unroll
    for (int b = 0; b < B; b++) acc[b] = make_float4(0.f, 0.f, 0.f, 0.f);

    #pragma unroll 4
    for (int ii = 0; ii < ICH2; ii++) {
        float4 w4 = *(const float4*)(wp + (size_t)ii * D);
        #pragma unroll
        for (int b = 0; b < B; b++) {
            float xv = xs[b][ii];
            acc[b].x = fmaf(xv, w4.x, acc[b].x);
            acc[b].y = fmaf(xv, w4.y, acc[b].y);
            acc[b].z = fmaf(xv, w4.z, acc[b].z);
            acc[b].w = fmaf(xv, w4.w, acc[b].w);
        }
    }
    #pragma unroll
    for (int b = 0; b < B; b++)
        *(float4*)&g_out_part[blockIdx.y][b][j] = acc[b];
}

// ---------------- kernel 5: final reduce -> d_out ----------------
__global__ void oproj_reduce(float* __restrict__ out) {
    const int t = blockIdx.x * 256 + threadIdx.x;
    const int b = t / D, j = t % D;
    float a = 0.f;
    #pragma unroll
    for (int s = 0; s < NSPLIT2; s++) a += g_out_part[s][b][j];
    out[(size_t)b * D + j] = a;
}

// ---------------- launch ----------------
extern "C" void kernel_launch(void* const* d_in, const int* in_sizes, int n_in,
                              void* d_out, int out_size) {
    const float* x        = (const float*)d_in[0];
    const float* fcos     = (const float*)d_in[1];
    const float* fsin     = (const float*)d_in[2];
    const float* mask     = (const float*)d_in[3];
    const float* cache_k  = (const float*)d_in[4];
    const float* cache_v  = (const float*)d_in[5];
    const int*   in_idx   = (const int*)d_in[7];
    const float* wq       = (const float*)d_in[9];
    const float* wk       = (const float*)d_in[10];
    const float* wv       = (const float*)d_in[11];
    const float* wo       = (const float*)d_in[12];

    float* out   = (float*)d_out;
    float* out_k = out + (size_t)B * D;
    float* out_v = out_k + (size_t)B * KVH * M * HD;

    static int smem_set = 0;
    if (!smem_set) {
        cudaFuncSetAttribute(attn_pass1, cudaFuncAttributeMaxDynamicSharedMemorySize, SMEM_BYTES);
        smem_set = 1;
    }

    proj_qkv<<<dim3(NCOLS / 1024, NSPLIT1), 256>>>(x, wq, wk, wv);
    rope_scatter<<<(B * NCOLS / 2) / 128, 128>>>(fcos, fsin);
    attn_pass1<<<B * KVH * MSPLIT, 256, SMEM_BYTES>>>(cache_k, cache_v, mask, in_idx, out_k, out_v);
    oproj<<<dim3(D / 1024, NSPLIT2), 256>>>(wo);
    oproj_reduce<<<(B * D) / 256, 256>>>(out);
}